// round 3
// baseline (speedup 1.0000x reference)
#include <cuda_runtime.h>
#include <cuda_bf16.h>
#include <cstdint>
#include <math.h>

#define B_    2
#define L_    2048
#define DIM_  1024
#define H_    16
#define DH_   64
#define N3_   3072
#define SCALE_ 0.125f
#define EPS_  1e-10f

// ---------------- device scratch (no allocation allowed) ----------------
__device__ float g_qkv[B_ * L_ * N3_];
__device__ float g_z[B_ * L_ * DIM_];
__device__ __nv_bfloat16 g_ahi[B_ * L_ * DIM_];
__device__ __nv_bfloat16 g_alo[B_ * L_ * DIM_];
__device__ __nv_bfloat16 g_wqt_hi[N3_ * DIM_];
__device__ __nv_bfloat16 g_wqt_lo[N3_ * DIM_];
__device__ __nv_bfloat16 g_wot_hi[DIM_ * DIM_];
__device__ __nv_bfloat16 g_wot_lo[DIM_ * DIM_];

// ---------------- helpers (arch-agnostic: sm_80+) ----------------
__device__ __forceinline__ uint32_t smem_u32(const void* p) {
    uint32_t a;
    asm("{ .reg .u64 t; cvta.to.shared.u64 t, %1; cvt.u32.u64 %0, t; }" : "=r"(a) : "l"(p));
    return a;
}
__device__ __forceinline__ void cpasync16(uint32_t s, const void* g) {
    asm volatile("cp.async.cg.shared.global [%0], [%1], 16;" :: "r"(s), "l"(g));
}
#define CP_COMMIT() asm volatile("cp.async.commit_group;")
#define CP_WAIT(n)  asm volatile("cp.async.wait_group %0;" :: "n"(n))

__device__ __forceinline__ void ldsm_x4(uint32_t r[4], uint32_t addr) {
    asm volatile("ldmatrix.sync.aligned.m8n8.x4.shared.b16 {%0,%1,%2,%3}, [%4];"
                 : "=r"(r[0]), "=r"(r[1]), "=r"(r[2]), "=r"(r[3]) : "r"(addr));
}
__device__ __forceinline__ void mma_bf16(float c[4], const uint32_t a[4], const uint32_t b[2]) {
    asm volatile(
        "mma.sync.aligned.m16n8k16.row.col.f32.bf16.bf16.f32 "
        "{%0,%1,%2,%3}, {%4,%5,%6,%7}, {%8,%9}, {%0,%1,%2,%3};"
        : "+f"(c[0]), "+f"(c[1]), "+f"(c[2]), "+f"(c[3])
        : "r"(a[0]), "r"(a[1]), "r"(a[2]), "r"(a[3]), "r"(b[0]), "r"(b[1]));
}

// ---------------------------------------------------------------------------
// fp32 -> (hi, lo) bf16 split
// ---------------------------------------------------------------------------
__global__ __launch_bounds__(256) void split_fp32(
    const float* __restrict__ in, __nv_bfloat16* __restrict__ hi,
    __nv_bfloat16* __restrict__ lo, int n4)
{
    int i = blockIdx.x * blockDim.x + threadIdx.x;
    if (i >= n4) return;
    float4 v = ((const float4*)in)[i];
    float vv[4] = {v.x, v.y, v.z, v.w};
    __nv_bfloat16 h[4], l[4];
#pragma unroll
    for (int k = 0; k < 4; k++) {
        h[k] = __float2bfloat16(vv[k]);
        l[k] = __float2bfloat16(vv[k] - __bfloat162float(h[k]));
    }
    ((uint2*)hi)[i] = *(uint2*)h;
    ((uint2*)lo)[i] = *(uint2*)l;
}

// ---------------------------------------------------------------------------
// fp32 [R,C] -> transposed split bf16 [C,R]
// ---------------------------------------------------------------------------
__global__ __launch_bounds__(256) void transpose_split(
    const float* __restrict__ in, __nv_bfloat16* __restrict__ ohi,
    __nv_bfloat16* __restrict__ olo, int R, int C)
{
    __shared__ float t[32][33];
    int cb = blockIdx.x * 32, rb = blockIdx.y * 32;
    int tx = threadIdx.x, ty = threadIdx.y;
#pragma unroll
    for (int i = 0; i < 4; i++)
        t[ty + 8 * i][tx] = in[(size_t)(rb + ty + 8 * i) * C + cb + tx];
    __syncthreads();
#pragma unroll
    for (int i = 0; i < 4; i++) {
        float v = t[tx][ty + 8 * i];
        __nv_bfloat16 h = __float2bfloat16(v);
        __nv_bfloat16 l = __float2bfloat16(v - __bfloat162float(h));
        size_t o = (size_t)(cb + ty + 8 * i) * R + rb + tx;
        ohi[o] = h;
        olo[o] = l;
    }
}

// ---------------------------------------------------------------------------
// HMMA bf16-split GEMM: C[M,N] = (Ahi+Alo)[M,K] @ (Bhi+Blo)[N,K]^T (+bias)
// CTA 128x128, 8 warps (warp tile 32x64), BK=32, cp.async double buffer.
// 3 passes per k16: hi*hi + lo*hi + hi*lo.
// smem per stage: 4 arrays of [128][40] bf16 (pad => conflict-free ldmatrix).
// ---------------------------------------------------------------------------
#define MMPAD 40
#define STG_BYTES (4 * 128 * MMPAD * 2)   // 40960
#define OFF_AH 0
#define OFF_AL (128 * MMPAD * 2)
#define OFF_BH (2 * 128 * MMPAD * 2)
#define OFF_BL (3 * 128 * MMPAD * 2)

template <bool BIAS>
__global__ __launch_bounds__(256, 1) void mm_hmma(
    const __nv_bfloat16* __restrict__ Ahi, const __nv_bfloat16* __restrict__ Alo,
    const __nv_bfloat16* __restrict__ Bhi, const __nv_bfloat16* __restrict__ Blo,
    const float* __restrict__ bias, float* __restrict__ C, int M, int N, int K)
{
    extern __shared__ char smem[];
    uint32_t sb = smem_u32(smem);
    int tid = threadIdx.x, wid = tid >> 5, lane = tid & 31;
    int m0 = blockIdx.y * 128, n0 = blockIdx.x * 128;
    int wm = wid & 3, wn = wid >> 2;

    const __nv_bfloat16* gAh = Ahi + (size_t)m0 * K;
    const __nv_bfloat16* gAl = Alo + (size_t)m0 * K;
    const __nv_bfloat16* gBh = Bhi + (size_t)n0 * K;
    const __nv_bfloat16* gBl = Blo + (size_t)n0 * K;

    // per-thread load mapping: 512 16B-chunks per array, 2 per thread
    int r0 = (tid + 0)   >> 2, c80 = ((tid + 0)   & 3) * 8;
    int r1 = (tid + 256) >> 2, c81 = ((tid + 256) & 3) * 8;

    float acc[2][8][4];
#pragma unroll
    for (int mi = 0; mi < 2; mi++)
#pragma unroll
        for (int ni = 0; ni < 8; ni++)
#pragma unroll
            for (int j = 0; j < 4; j++) acc[mi][ni][j] = 0.0f;

    const int NCH = K >> 5;  // K/32

    // ldmatrix address components
    uint32_t a_row = wm * 32 + (lane & 15);
    uint32_t a_k8  = (lane >> 4) * 8;
    uint32_t b_row = wn * 64 + (lane & 7) + ((lane >> 4) << 3);
    uint32_t b_k8  = ((lane >> 3) & 1) * 8;

    // prologue: stage 0
    {
        size_t go0 = (size_t)r0 * K + c80, go1 = (size_t)r1 * K + c81;
        uint32_t so0 = (r0 * MMPAD + c80) * 2, so1 = (r1 * MMPAD + c81) * 2;
        cpasync16(sb + OFF_AH + so0, gAh + go0); cpasync16(sb + OFF_AH + so1, gAh + go1);
        cpasync16(sb + OFF_AL + so0, gAl + go0); cpasync16(sb + OFF_AL + so1, gAl + go1);
        cpasync16(sb + OFF_BH + so0, gBh + go0); cpasync16(sb + OFF_BH + so1, gBh + go1);
        cpasync16(sb + OFF_BL + so0, gBl + go0); cpasync16(sb + OFF_BL + so1, gBl + go1);
        CP_COMMIT();
    }

    for (int c = 0; c < NCH; c++) {
        if (c + 1 < NCH) {
            uint32_t stg = sb + ((c + 1) & 1) * STG_BYTES;
            int kc = (c + 1) * 32;
            size_t go0 = (size_t)r0 * K + kc + c80, go1 = (size_t)r1 * K + kc + c81;
            uint32_t so0 = (r0 * MMPAD + c80) * 2, so1 = (r1 * MMPAD + c81) * 2;
            cpasync16(stg + OFF_AH + so0, gAh + go0); cpasync16(stg + OFF_AH + so1, gAh + go1);
            cpasync16(stg + OFF_AL + so0, gAl + go0); cpasync16(stg + OFF_AL + so1, gAl + go1);
            cpasync16(stg + OFF_BH + so0, gBh + go0); cpasync16(stg + OFF_BH + so1, gBh + go1);
            cpasync16(stg + OFF_BL + so0, gBl + go0); cpasync16(stg + OFF_BL + so1, gBl + go1);
            CP_COMMIT();
            CP_WAIT(1);
        } else {
            CP_WAIT(0);
        }
        __syncthreads();

        uint32_t stg = sb + (c & 1) * STG_BYTES;
#pragma unroll
        for (int ks = 0; ks < 2; ks++) {
            uint32_t ah[2][4], al[2][4], bh[4][4], bl[4][4];
#pragma unroll
            for (int mi = 0; mi < 2; mi++) {
                uint32_t ao = ((a_row + mi * 16) * MMPAD + ks * 16 + a_k8) * 2;
                ldsm_x4(ah[mi], stg + OFF_AH + ao);
                ldsm_x4(al[mi], stg + OFF_AL + ao);
            }
#pragma unroll
            for (int nb = 0; nb < 4; nb++) {
                uint32_t bo = ((b_row + nb * 16) * MMPAD + ks * 16 + b_k8) * 2;
                ldsm_x4(bh[nb], stg + OFF_BH + bo);
                ldsm_x4(bl[nb], stg + OFF_BL + bo);
            }
#pragma unroll
            for (int mi = 0; mi < 2; mi++)
#pragma unroll
                for (int ni = 0; ni < 8; ni++)
                    mma_bf16(acc[mi][ni], ah[mi], &bh[ni >> 1][(ni & 1) * 2]);
#pragma unroll
            for (int mi = 0; mi < 2; mi++)
#pragma unroll
                for (int ni = 0; ni < 8; ni++)
                    mma_bf16(acc[mi][ni], al[mi], &bh[ni >> 1][(ni & 1) * 2]);
#pragma unroll
            for (int mi = 0; mi < 2; mi++)
#pragma unroll
                for (int ni = 0; ni < 8; ni++)
                    mma_bf16(acc[mi][ni], ah[mi], &bl[ni >> 1][(ni & 1) * 2]);
        }
        __syncthreads();
    }

    // epilogue
    int rbase = m0 + wm * 32 + (lane >> 2);
    int cb0 = n0 + wn * 64 + (lane & 3) * 2;
#pragma unroll
    for (int mi = 0; mi < 2; mi++) {
#pragma unroll
        for (int ni = 0; ni < 8; ni++) {
            int rr = rbase + mi * 16;
            int cc = cb0 + ni * 8;
            float b0 = 0.f, b1 = 0.f;
            if (BIAS) { b0 = bias[cc]; b1 = bias[cc + 1]; }
            float2 v0 = {acc[mi][ni][0] + b0, acc[mi][ni][1] + b1};
            float2 v1 = {acc[mi][ni][2] + b0, acc[mi][ni][3] + b1};
            *(float2*)&C[(size_t)rr * N + cc] = v0;
            *(float2*)&C[(size_t)(rr + 8) * N + cc] = v1;
        }
    }
}

// ---------------------------------------------------------------------------
// Flash attention (fp32 SIMT), post-softmax multiplicative mask + renorm.
// Q tile 64, KV block 64, 128 threads, 8x4 microtile, mask from gmem.
// ---------------------------------------------------------------------------
__global__ __launch_bounds__(128) void attn_kernel(
    const float* __restrict__ qkv, const float* __restrict__ mask,
    float* __restrict__ z)
{
    const int ST = 68;
    extern __shared__ float sm[];
    float* QT = sm;             // [d][r]
    float* KT = QT + 64 * ST;   // [d][c]
    float* Vs = KT + 64 * ST;   // [k][c]
    float* S  = Vs + 64 * ST;   // [r][c]
    float* PT = S  + 64 * ST;   // [k][r]
    __shared__ float m_s[64], Zf[64], Lm[64], corr[64];

    int tid = threadIdx.x;
    int lane = tid & 31, warp = tid >> 5;
    int b = blockIdx.z, h = blockIdx.y;
    int q0 = blockIdx.x * 64;

    const float* qbase = qkv + (size_t)b * L_ * N3_ + h * DH_;
    const float* kbase = qbase + 1024;
    const float* vbase = qbase + 2048;
    const float* mbase = mask + ((size_t)b * L_ + q0) * L_;

    for (int idx = tid; idx < 64 * 64; idx += 128) {
        int r = idx >> 6, d = idx & 63;
        QT[d * ST + r] = qbase[(size_t)(q0 + r) * N3_ + d] * SCALE_;
    }
    if (tid < 64) { m_s[tid] = -INFINITY; Zf[tid] = 0.0f; Lm[tid] = 0.0f; }

    int tr8 = (tid >> 4) * 8;
    int tc4 = (tid & 15) * 4;
    float oacc[8][4] = {};
    __syncthreads();

    for (int k0 = 0; k0 < L_; k0 += 64) {
        for (int idx = tid; idx < 64 * 64; idx += 128) {
            int c = idx >> 6, d = idx & 63;
            KT[d * ST + c] = kbase[(size_t)(k0 + c) * N3_ + d];
        }
        for (int idx = tid; idx < 64 * 64; idx += 128) {
            int j = idx >> 6, c = idx & 63;
            Vs[j * ST + c] = vbase[(size_t)(k0 + j) * N3_ + c];
        }
        __syncthreads();

        // S = (Q*scale) @ K^T
        {
            float sacc[8][4] = {};
#pragma unroll 4
            for (int kk = 0; kk < 64; kk++) {
                float4 qa = *(const float4*)&QT[kk * ST + tr8];
                float4 qb = *(const float4*)&QT[kk * ST + tr8 + 4];
                float4 kv = *(const float4*)&KT[kk * ST + tc4];
                float qv[8] = {qa.x, qa.y, qa.z, qa.w, qb.x, qb.y, qb.z, qb.w};
                float kr[4] = {kv.x, kv.y, kv.z, kv.w};
#pragma unroll
                for (int i = 0; i < 8; i++)
#pragma unroll
                    for (int j = 0; j < 4; j++)
                        sacc[i][j] += qv[i] * kr[j];
            }
#pragma unroll
            for (int i = 0; i < 8; i++) {
                float4 v;
                v.x = sacc[i][0]; v.y = sacc[i][1]; v.z = sacc[i][2]; v.w = sacc[i][3];
                *(float4*)&S[(tr8 + i) * ST + tc4] = v;
            }
        }
        __syncthreads();

        // online softmax: warp w owns rows w*16 .. w*16+15
#pragma unroll
        for (int i = 0; i < 16; i++) {
            int r = warp * 16 + i;
            float s0 = S[r * ST + lane];
            float s1 = S[r * ST + 32 + lane];
            float mk0 = mbase[(size_t)r * L_ + k0 + lane];
            float mk1 = mbase[(size_t)r * L_ + k0 + 32 + lane];
            float mx = fmaxf(s0, s1);
#pragma unroll
            for (int o = 16; o > 0; o >>= 1)
                mx = fmaxf(mx, __shfl_xor_sync(0xffffffffu, mx, o));
            float mprev = m_s[r];
            float mnew = fmaxf(mprev, mx);
            float cfac = __expf(mprev - mnew);
            float p0 = __expf(s0 - mnew);
            float p1 = __expf(s1 - mnew);
            float zs = p0 + p1;
            float pm0 = p0 * mk0;
            float pm1 = p1 * mk1;
            float ls = pm0 + pm1;
#pragma unroll
            for (int o = 16; o > 0; o >>= 1) {
                zs += __shfl_xor_sync(0xffffffffu, zs, o);
                ls += __shfl_xor_sync(0xffffffffu, ls, o);
            }
            PT[lane * ST + r] = pm0;
            PT[(lane + 32) * ST + r] = pm1;
            if (lane == 0) {
                m_s[r] = mnew;
                Zf[r] = Zf[r] * cfac + zs;
                Lm[r] = Lm[r] * cfac + ls;
                corr[r] = cfac;
            }
        }
        __syncthreads();

        // O = O*corr + P @ V
        {
            float cr[8];
#pragma unroll
            for (int i = 0; i < 8; i++) cr[i] = corr[tr8 + i];
#pragma unroll
            for (int i = 0; i < 8; i++)
#pragma unroll
                for (int j = 0; j < 4; j++) oacc[i][j] *= cr[i];
#pragma unroll 4
            for (int kk = 0; kk < 64; kk++) {
                float4 pa = *(const float4*)&PT[kk * ST + tr8];
                float4 pb = *(const float4*)&PT[kk * ST + tr8 + 4];
                float4 vv = *(const float4*)&Vs[kk * ST + tc4];
                float pv[8] = {pa.x, pa.y, pa.z, pa.w, pb.x, pb.y, pb.z, pb.w};
                float vr[4] = {vv.x, vv.y, vv.z, vv.w};
#pragma unroll
                for (int i = 0; i < 8; i++)
#pragma unroll
                    for (int j = 0; j < 4; j++)
                        oacc[i][j] += pv[i] * vr[j];
            }
        }
        __syncthreads();
    }

#pragma unroll
    for (int i = 0; i < 8; i++) {
        int r = tr8 + i;
        float inv = 1.0f / (Lm[r] + EPS_ * Zf[r]);
        float4 v;
        v.x = oacc[i][0] * inv; v.y = oacc[i][1] * inv;
        v.z = oacc[i][2] * inv; v.w = oacc[i][3] * inv;
        *(float4*)&z[((size_t)b * L_ + q0 + r) * DIM_ + h * DH_ + tc4] = v;
    }
}

// ---------------------------------------------------------------------------
extern "C" void kernel_launch(void* const* d_in, const int* in_sizes, int n_in,
                              void* d_out, int out_size)
{
    const float* x    = (const float*)d_in[0];
    const float* mask = (const float*)d_in[1];
    const float* Wqkv = (const float*)d_in[2];   // [1024, 3072]
    const float* Wout = (const float*)d_in[3];   // [1024, 1024]
    const float* bout = (const float*)d_in[4];
    float* out = (float*)d_out;

    float *qkvp = nullptr, *zp = nullptr;
    __nv_bfloat16 *ahi, *alo, *wqh, *wql, *woh, *wol;
    cudaGetSymbolAddress((void**)&qkvp, g_qkv);
    cudaGetSymbolAddress((void**)&zp,   g_z);
    cudaGetSymbolAddress((void**)&ahi,  g_ahi);
    cudaGetSymbolAddress((void**)&alo,  g_alo);
    cudaGetSymbolAddress((void**)&wqh,  g_wqt_hi);
    cudaGetSymbolAddress((void**)&wql,  g_wqt_lo);
    cudaGetSymbolAddress((void**)&woh,  g_wot_hi);
    cudaGetSymbolAddress((void**)&wol,  g_wot_lo);

    const int GSM = 2 * STG_BYTES;                    // 81920 B
    const int ASM = 5 * 64 * 68 * (int)sizeof(float); // 87040 B
    cudaFuncSetAttribute(mm_hmma<false>, cudaFuncAttributeMaxDynamicSharedMemorySize, GSM);
    cudaFuncSetAttribute(mm_hmma<true>,  cudaFuncAttributeMaxDynamicSharedMemorySize, GSM);
    cudaFuncSetAttribute(attn_kernel,    cudaFuncAttributeMaxDynamicSharedMemorySize, ASM);

    split_fp32<<<(B_ * L_ * DIM_ / 4 + 255) / 256, 256>>>(x, ahi, alo, B_ * L_ * DIM_ / 4);
    transpose_split<<<dim3(N3_ / 32, DIM_ / 32), dim3(32, 8)>>>(Wqkv, wqh, wql, DIM_, N3_);
    transpose_split<<<dim3(DIM_ / 32, DIM_ / 32), dim3(32, 8)>>>(Wout, woh, wol, DIM_, DIM_);

    mm_hmma<false><<<dim3(N3_ / 128, (B_ * L_) / 128), 256, GSM>>>(
        ahi, alo, wqh, wql, nullptr, qkvp, B_ * L_, N3_, DIM_);

    attn_kernel<<<dim3(L_ / 64, H_, B_), 128, ASM>>>(qkvp, mask, zp);

    split_fp32<<<(B_ * L_ * DIM_ / 4 + 255) / 256, 256>>>(zp, ahi, alo, B_ * L_ * DIM_ / 4);
    mm_hmma<true><<<dim3(DIM_ / 128, (B_ * L_) / 128), 256, GSM>>>(
        ahi, alo, woh, wol, bout, out, B_ * L_, DIM_, DIM_);
}

// round 5
// speedup vs baseline: 3.4413x; 3.4413x over previous
#include <cuda_runtime.h>
#include <cuda_bf16.h>
#include <cstdint>
#include <math.h>

#define B_    2
#define L_    2048
#define DIM_  1024
#define H_    16
#define DH_   64
#define N3_   3072
#define SCALE_ 0.125f
#define EPS_  1e-10f

// ---------------- device scratch ----------------
__device__ float g_qkv[B_ * L_ * N3_];
__device__ __nv_bfloat16 g_ahi[B_ * L_ * DIM_];
__device__ __nv_bfloat16 g_alo[B_ * L_ * DIM_];
__device__ __nv_bfloat16 g_wqt_hi[N3_ * DIM_];
__device__ __nv_bfloat16 g_wqt_lo[N3_ * DIM_];
__device__ __nv_bfloat16 g_wot_hi[DIM_ * DIM_];
__device__ __nv_bfloat16 g_wot_lo[DIM_ * DIM_];
// attention operand layouts
__device__ __nv_bfloat16 g_qh[B_ * H_ * L_ * DH_];   // [b,h,l,d] (scaled)
__device__ __nv_bfloat16 g_ql[B_ * H_ * L_ * DH_];
__device__ __nv_bfloat16 g_kh[B_ * H_ * L_ * DH_];
__device__ __nv_bfloat16 g_kl[B_ * H_ * L_ * DH_];
__device__ __nv_bfloat16 g_vth[B_ * H_ * DH_ * L_];  // [b,h,d,l] transposed
__device__ __nv_bfloat16 g_vtl[B_ * H_ * DH_ * L_];
__device__ __nv_bfloat16 g_maskb[B_ * L_ * L_];

// ---------------- helpers ----------------
__device__ __forceinline__ uint32_t smem_u32(const void* p) {
    uint32_t a;
    asm("{ .reg .u64 t; cvta.to.shared.u64 t, %1; cvt.u32.u64 %0, t; }" : "=r"(a) : "l"(p));
    return a;
}
__device__ __forceinline__ void cpasync16(uint32_t s, const void* g) {
    asm volatile("cp.async.cg.shared.global [%0], [%1], 16;" :: "r"(s), "l"(g));
}
#define CP_COMMIT() asm volatile("cp.async.commit_group;")
#define CP_WAIT(n)  asm volatile("cp.async.wait_group %0;" :: "n"(n))

__device__ __forceinline__ void ldsm_x4(uint32_t r[4], uint32_t addr) {
    asm volatile("ldmatrix.sync.aligned.m8n8.x4.shared.b16 {%0,%1,%2,%3}, [%4];"
                 : "=r"(r[0]), "=r"(r[1]), "=r"(r[2]), "=r"(r[3]) : "r"(addr));
}
__device__ __forceinline__ void mma_bf16(float c[4], const uint32_t a[4], const uint32_t b[2]) {
    asm volatile(
        "mma.sync.aligned.m16n8k16.row.col.f32.bf16.bf16.f32 "
        "{%0,%1,%2,%3}, {%4,%5,%6,%7}, {%8,%9}, {%0,%1,%2,%3};"
        : "+f"(c[0]), "+f"(c[1]), "+f"(c[2]), "+f"(c[3])
        : "r"(a[0]), "r"(a[1]), "r"(a[2]), "r"(a[3]), "r"(b[0]), "r"(b[1]));
}
__device__ __forceinline__ uint32_t bfpack(float lo, float hi) {
    uint32_t r;
    asm("cvt.rn.bf16x2.f32 %0, %1, %2;" : "=r"(r) : "f"(hi), "f"(lo));
    return r;
}
__device__ __forceinline__ float bf_lo(uint32_t u) { return __uint_as_float(u << 16); }
__device__ __forceinline__ float bf_hi(uint32_t u) { return __uint_as_float(u & 0xffff0000u); }
__device__ __forceinline__ uint32_t lds32(uint32_t a) {
    uint32_t v;
    asm volatile("ld.shared.b32 %0, [%1];" : "=r"(v) : "r"(a));
    return v;
}

// ---------------------------------------------------------------------------
// fp32 -> (hi, lo) bf16 split
// ---------------------------------------------------------------------------
__global__ __launch_bounds__(256) void split_fp32(
    const float* __restrict__ in, __nv_bfloat16* __restrict__ hi,
    __nv_bfloat16* __restrict__ lo, int n4)
{
    int i = blockIdx.x * blockDim.x + threadIdx.x;
    if (i >= n4) return;
    float4 v = ((const float4*)in)[i];
    float vv[4] = {v.x, v.y, v.z, v.w};
    __nv_bfloat16 h[4], l[4];
#pragma unroll
    for (int k = 0; k < 4; k++) {
        h[k] = __float2bfloat16(vv[k]);
        l[k] = __float2bfloat16(vv[k] - __bfloat162float(h[k]));
    }
    ((uint2*)hi)[i] = *(uint2*)h;
    ((uint2*)lo)[i] = *(uint2*)l;
}

// fp32 mask -> bf16 (values 0/1 exact)
__global__ __launch_bounds__(256) void mask_bf16(
    const float* __restrict__ in, __nv_bfloat16* __restrict__ o, int n4)
{
    int i = blockIdx.x * blockDim.x + threadIdx.x;
    if (i >= n4) return;
    float4 v = ((const float4*)in)[i];
    __nv_bfloat16 h[4] = {__float2bfloat16(v.x), __float2bfloat16(v.y),
                          __float2bfloat16(v.z), __float2bfloat16(v.w)};
    ((uint2*)o)[i] = *(uint2*)h;
}

// ---------------------------------------------------------------------------
// fp32 [R,C] -> transposed split bf16 [C,R] (weights)
// ---------------------------------------------------------------------------
__global__ __launch_bounds__(256) void transpose_split(
    const float* __restrict__ in, __nv_bfloat16* __restrict__ ohi,
    __nv_bfloat16* __restrict__ olo, int R, int C)
{
    __shared__ float t[32][33];
    int cb = blockIdx.x * 32, rb = blockIdx.y * 32;
    int tx = threadIdx.x, ty = threadIdx.y;
#pragma unroll
    for (int i = 0; i < 4; i++)
        t[ty + 8 * i][tx] = in[(size_t)(rb + ty + 8 * i) * C + cb + tx];
    __syncthreads();
#pragma unroll
    for (int i = 0; i < 4; i++) {
        float v = t[tx][ty + 8 * i];
        __nv_bfloat16 h = __float2bfloat16(v);
        __nv_bfloat16 l = __float2bfloat16(v - __bfloat162float(h));
        size_t o = (size_t)(cb + ty + 8 * i) * R + rb + tx;
        ohi[o] = h;
        olo[o] = l;
    }
}

// ---------------------------------------------------------------------------
// qkv fp32 [b,l,3072] -> Q (scaled) and K split bf16 [b,h,l,64]
// ---------------------------------------------------------------------------
__global__ __launch_bounds__(256) void qk_relayout(
    const float* __restrict__ qkv,
    __nv_bfloat16* __restrict__ qh, __nv_bfloat16* __restrict__ ql,
    __nv_bfloat16* __restrict__ kh, __nv_bfloat16* __restrict__ kl)
{
    int i = blockIdx.x * 256 + threadIdx.x;   // over B*L*256 (d4 groups)
    int bl = i >> 8;
    int hd = (i & 255) * 4;
    int b = bl >> 11, l = bl & 2047;
    int h = hd >> 6, d = hd & 63;
    const float* src = qkv + (size_t)bl * N3_ + hd;
    float4 q = *(const float4*)src;
    float4 k = *(const float4*)(src + 1024);
    size_t dst = ((size_t)(b * H_ + h) * L_ + l) * DH_ + d;
    float qv[4] = {q.x * SCALE_, q.y * SCALE_, q.z * SCALE_, q.w * SCALE_};
    float kv[4] = {k.x, k.y, k.z, k.w};
    __nv_bfloat16 qhh[4], qll[4], khh[4], kll[4];
#pragma unroll
    for (int e = 0; e < 4; e++) {
        qhh[e] = __float2bfloat16(qv[e]);
        qll[e] = __float2bfloat16(qv[e] - __bfloat162float(qhh[e]));
        khh[e] = __float2bfloat16(kv[e]);
        kll[e] = __float2bfloat16(kv[e] - __bfloat162float(khh[e]));
    }
    *(uint2*)(qh + dst) = *(uint2*)qhh;
    *(uint2*)(ql + dst) = *(uint2*)qll;
    *(uint2*)(kh + dst) = *(uint2*)khh;
    *(uint2*)(kl + dst) = *(uint2*)kll;
}

// ---------------------------------------------------------------------------
// V from qkv fp32 -> transposed split bf16 [b,h,64,L]
// ---------------------------------------------------------------------------
__global__ __launch_bounds__(256) void v_relayout(
    const float* __restrict__ qkv,
    __nv_bfloat16* __restrict__ vth, __nv_bfloat16* __restrict__ vtl)
{
    __shared__ float t[32][33];
    int bh = blockIdx.z;
    int b = bh >> 4, h = bh & 15;
    int l0 = blockIdx.x * 32, d0 = blockIdx.y * 32;
    int tx = threadIdx.x, ty = threadIdx.y;
#pragma unroll
    for (int i = 0; i < 4; i++)
        t[ty + 8 * i][tx] =
            qkv[((size_t)b * L_ + l0 + ty + 8 * i) * N3_ + 2048 + h * 64 + d0 + tx];
    __syncthreads();
#pragma unroll
    for (int i = 0; i < 4; i++) {
        float v = t[tx][ty + 8 * i];   // element (l = l0+tx, d = d0+ty+8i)
        __nv_bfloat16 hh = __float2bfloat16(v);
        __nv_bfloat16 ll = __float2bfloat16(v - __bfloat162float(hh));
        size_t o = ((size_t)bh * DH_ + d0 + ty + 8 * i) * L_ + l0 + tx;
        vth[o] = hh;
        vtl[o] = ll;
    }
}

// ---------------------------------------------------------------------------
// HMMA bf16-split GEMM (validated in round 3: tensor=45.8%)
// ---------------------------------------------------------------------------
#define MMPAD 40
#define STG_BYTES (4 * 128 * MMPAD * 2)
#define OFF_AH 0
#define OFF_AL (128 * MMPAD * 2)
#define OFF_BH (2 * 128 * MMPAD * 2)
#define OFF_BL (3 * 128 * MMPAD * 2)

template <bool BIAS>
__global__ __launch_bounds__(256, 1) void mm_hmma(
    const __nv_bfloat16* __restrict__ Ahi, const __nv_bfloat16* __restrict__ Alo,
    const __nv_bfloat16* __restrict__ Bhi, const __nv_bfloat16* __restrict__ Blo,
    const float* __restrict__ bias, float* __restrict__ C, int M, int N, int K)
{
    extern __shared__ char smem[];
    uint32_t sb = smem_u32(smem);
    int tid = threadIdx.x, wid = tid >> 5, lane = tid & 31;
    int m0 = blockIdx.y * 128, n0 = blockIdx.x * 128;
    int wm = wid & 3, wn = wid >> 2;

    const __nv_bfloat16* gAh = Ahi + (size_t)m0 * K;
    const __nv_bfloat16* gAl = Alo + (size_t)m0 * K;
    const __nv_bfloat16* gBh = Bhi + (size_t)n0 * K;
    const __nv_bfloat16* gBl = Blo + (size_t)n0 * K;

    int r0 = (tid + 0) >> 2, c80 = ((tid + 0) & 3) * 8;
    int r1 = (tid + 256) >> 2, c81 = ((tid + 256) & 3) * 8;

    float acc[2][8][4];
#pragma unroll
    for (int mi = 0; mi < 2; mi++)
#pragma unroll
        for (int ni = 0; ni < 8; ni++)
#pragma unroll
            for (int j = 0; j < 4; j++) acc[mi][ni][j] = 0.0f;

    const int NCH = K >> 5;
    uint32_t a_row = wm * 32 + (lane & 15);
    uint32_t a_k8 = (lane >> 4) * 8;
    uint32_t b_row = wn * 64 + (lane & 7) + ((lane >> 4) << 3);
    uint32_t b_k8 = ((lane >> 3) & 1) * 8;

    {
        size_t go0 = (size_t)r0 * K + c80, go1 = (size_t)r1 * K + c81;
        uint32_t so0 = (r0 * MMPAD + c80) * 2, so1 = (r1 * MMPAD + c81) * 2;
        cpasync16(sb + OFF_AH + so0, gAh + go0); cpasync16(sb + OFF_AH + so1, gAh + go1);
        cpasync16(sb + OFF_AL + so0, gAl + go0); cpasync16(sb + OFF_AL + so1, gAl + go1);
        cpasync16(sb + OFF_BH + so0, gBh + go0); cpasync16(sb + OFF_BH + so1, gBh + go1);
        cpasync16(sb + OFF_BL + so0, gBl + go0); cpasync16(sb + OFF_BL + so1, gBl + go1);
        CP_COMMIT();
    }

    for (int c = 0; c < NCH; c++) {
        if (c + 1 < NCH) {
            uint32_t stg = sb + ((c + 1) & 1) * STG_BYTES;
            int kc = (c + 1) * 32;
            size_t go0 = (size_t)r0 * K + kc + c80, go1 = (size_t)r1 * K + kc + c81;
            uint32_t so0 = (r0 * MMPAD + c80) * 2, so1 = (r1 * MMPAD + c81) * 2;
            cpasync16(stg + OFF_AH + so0, gAh + go0); cpasync16(stg + OFF_AH + so1, gAh + go1);
            cpasync16(stg + OFF_AL + so0, gAl + go0); cpasync16(stg + OFF_AL + so1, gAl + go1);
            cpasync16(stg + OFF_BH + so0, gBh + go0); cpasync16(stg + OFF_BH + so1, gBh + go1);
            cpasync16(stg + OFF_BL + so0, gBl + go0); cpasync16(stg + OFF_BL + so1, gBl + go1);
            CP_COMMIT();
            CP_WAIT(1);
        } else {
            CP_WAIT(0);
        }
        __syncthreads();

        uint32_t stg = sb + (c & 1) * STG_BYTES;
#pragma unroll
        for (int ks = 0; ks < 2; ks++) {
            uint32_t ah[2][4], al[2][4], bh[4][4], bl[4][4];
#pragma unroll
            for (int mi = 0; mi < 2; mi++) {
                uint32_t ao = ((a_row + mi * 16) * MMPAD + ks * 16 + a_k8) * 2;
                ldsm_x4(ah[mi], stg + OFF_AH + ao);
                ldsm_x4(al[mi], stg + OFF_AL + ao);
            }
#pragma unroll
            for (int nb = 0; nb < 4; nb++) {
                uint32_t bo = ((b_row + nb * 16) * MMPAD + ks * 16 + b_k8) * 2;
                ldsm_x4(bh[nb], stg + OFF_BH + bo);
                ldsm_x4(bl[nb], stg + OFF_BL + bo);
            }
#pragma unroll
            for (int mi = 0; mi < 2; mi++)
#pragma unroll
                for (int ni = 0; ni < 8; ni++)
                    mma_bf16(acc[mi][ni], ah[mi], &bh[ni >> 1][(ni & 1) * 2]);
#pragma unroll
            for (int mi = 0; mi < 2; mi++)
#pragma unroll
                for (int ni = 0; ni < 8; ni++)
                    mma_bf16(acc[mi][ni], al[mi], &bh[ni >> 1][(ni & 1) * 2]);
#pragma unroll
            for (int mi = 0; mi < 2; mi++)
#pragma unroll
                for (int ni = 0; ni < 8; ni++)
                    mma_bf16(acc[mi][ni], ah[mi], &bl[ni >> 1][(ni & 1) * 2]);
        }
        __syncthreads();
    }

    int rbase = m0 + wm * 32 + (lane >> 2);
    int cb0 = n0 + wn * 64 + (lane & 3) * 2;
#pragma unroll
    for (int mi = 0; mi < 2; mi++) {
#pragma unroll
        for (int ni = 0; ni < 8; ni++) {
            int rr = rbase + mi * 16;
            int cc = cb0 + ni * 8;
            float b0 = 0.f, b1 = 0.f;
            if (BIAS) { b0 = bias[cc]; b1 = bias[cc + 1]; }
            float2 v0 = {acc[mi][ni][0] + b0, acc[mi][ni][1] + b1};
            float2 v1 = {acc[mi][ni][2] + b0, acc[mi][ni][3] + b1};
            *(float2*)&C[(size_t)rr * N + cc] = v0;
            *(float2*)&C[(size_t)(rr + 8) * N + cc] = v1;
        }
    }
}

// ---------------------------------------------------------------------------
// Tensor-core flash attention (bf16 split), post-softmax mask + renorm.
// Q tile 128 x KV block 64, 8 warps (m16/warp), FA2 register softmax.
// Outputs z directly as split bf16 (feeds out-projection GEMM).
// ---------------------------------------------------------------------------
#define RSTRIDE 144                         // 72 bf16 per row (64 + 8 pad)
#define AOFF_QH 0
#define AOFF_QL 18432
#define ASTAGE0 36864
#define AOFF_KH 0
#define AOFF_KL 9216
#define AOFF_VH 18432
#define AOFF_VL 27648
#define AOFF_MS 36864
#define ASTAGE_SZ 55296
#define ATTN_SMEM_TOTAL (ASTAGE0 + 2 * ASTAGE_SZ)   // 147456

__global__ __launch_bounds__(256, 1) void attn_mma(
    const __nv_bfloat16* __restrict__ Qh, const __nv_bfloat16* __restrict__ Ql,
    const __nv_bfloat16* __restrict__ Kh, const __nv_bfloat16* __restrict__ Kl,
    const __nv_bfloat16* __restrict__ Vth, const __nv_bfloat16* __restrict__ Vtl,
    const __nv_bfloat16* __restrict__ maskb,
    __nv_bfloat16* __restrict__ zhi, __nv_bfloat16* __restrict__ zlo)
{
    extern __shared__ char smem[];
    uint32_t sb = smem_u32(smem);
    int tid = threadIdx.x, wid = tid >> 5, lane = tid & 31;
    int b = blockIdx.z, h = blockIdx.y, q0 = blockIdx.x * 128;

    size_t headoff = (size_t)(b * H_ + h) * L_ * DH_;
    const __nv_bfloat16* gQh = Qh + headoff + (size_t)q0 * DH_;
    const __nv_bfloat16* gQl = Ql + headoff + (size_t)q0 * DH_;
    const __nv_bfloat16* gKh = Kh + headoff;
    const __nv_bfloat16* gKl = Kl + headoff;
    const __nv_bfloat16* gVh = Vth + headoff;   // [64][L]
    const __nv_bfloat16* gVl = Vtl + headoff;
    const __nv_bfloat16* gMk = maskb + ((size_t)b * L_ + q0) * L_;

    auto load_stage = [&](int j, int s) {
        uint32_t stg = sb + ASTAGE0 + s * ASTAGE_SZ;
        int k0 = j * 64;
#pragma unroll
        for (int t = 0; t < 4; t++) {
            int u = tid + 256 * t;
            int isLo = u >> 9;
            int idx = u & 511;
            int row = idx >> 3, c8 = idx & 7;
            const __nv_bfloat16* sk = (isLo ? gKl : gKh) + (size_t)(k0 + row) * DH_ + c8 * 8;
            cpasync16(stg + (isLo ? AOFF_KL : AOFF_KH) + row * RSTRIDE + c8 * 16, sk);
            const __nv_bfloat16* sv = (isLo ? gVl : gVh) + (size_t)row * L_ + k0 + c8 * 8;
            cpasync16(stg + (isLo ? AOFF_VL : AOFF_VH) + row * RSTRIDE + c8 * 16, sv);
        }
#pragma unroll
        for (int t = 0; t < 4; t++) {
            int u = tid + 256 * t;
            int row = u >> 3, c8 = u & 7;
            cpasync16(stg + AOFF_MS + row * RSTRIDE + c8 * 16,
                      gMk + (size_t)row * L_ + k0 + c8 * 8);
        }
    };

    // prologue: Q + stage 0 as group 0
    {
#pragma unroll
        for (int t = 0; t < 8; t++) {
            int u = tid + 256 * t;
            int isLo = u >> 10;
            int idx = u & 1023;
            int row = idx >> 3, c8 = idx & 7;
            const __nv_bfloat16* sq = (isLo ? gQl : gQh) + (size_t)row * DH_ + c8 * 8;
            cpasync16(sb + (isLo ? AOFF_QL : AOFF_QH) + row * RSTRIDE + c8 * 16, sq);
        }
        load_stage(0, 0);
        CP_COMMIT();
    }

    int r0 = lane >> 2, quad = lane & 3;
    uint32_t a_base = (wid * 16 + (lane & 15)) * RSTRIDE + (lane >> 4) * 16;
    uint32_t b_base = ((lane & 7) + ((lane >> 4) << 3)) * RSTRIDE + ((lane >> 3) & 1) * 16;

    float o[8][4];
#pragma unroll
    for (int i = 0; i < 8; i++)
#pragma unroll
        for (int j = 0; j < 4; j++) o[i][j] = 0.0f;
    float mpr0 = -INFINITY, mpr1 = -INFINITY;
    float Zf0 = 0.f, Zf1 = 0.f, Lm0 = 0.f, Lm1 = 0.f;
    uint32_t qfh[4][4], qfl[4][4];

    for (int j = 0; j < 32; j++) {
        if (j + 1 < 32) { load_stage(j + 1, (j + 1) & 1); CP_COMMIT(); CP_WAIT(1); }
        else           { CP_WAIT(0); }
        __syncthreads();

        if (j == 0) {
#pragma unroll
            for (int ks = 0; ks < 4; ks++) {
                ldsm_x4(qfh[ks], sb + AOFF_QH + a_base + ks * 32);
                ldsm_x4(qfl[ks], sb + AOFF_QL + a_base + ks * 32);
            }
        }
        uint32_t stg = sb + ASTAGE0 + (j & 1) * ASTAGE_SZ;

        // ---- S = Q K^T (3-way split) ----
        float s[8][4];
#pragma unroll
        for (int i = 0; i < 8; i++)
#pragma unroll
            for (int e = 0; e < 4; e++) s[i][e] = 0.0f;
#pragma unroll
        for (int ks = 0; ks < 4; ks++) {
            uint32_t kh[4][4], kl[4][4];
#pragma unroll
            for (int np = 0; np < 4; np++) {
                uint32_t ad = stg + np * (16 * RSTRIDE) + ks * 32 + b_base;
                ldsm_x4(kh[np], ad + AOFF_KH);
                ldsm_x4(kl[np], ad + AOFF_KL);
            }
#pragma unroll
            for (int nf = 0; nf < 8; nf++) {
                mma_bf16(s[nf], qfh[ks], &kh[nf >> 1][(nf & 1) * 2]);
                mma_bf16(s[nf], qfl[ks], &kh[nf >> 1][(nf & 1) * 2]);
                mma_bf16(s[nf], qfh[ks], &kl[nf >> 1][(nf & 1) * 2]);
            }
        }

        // ---- online softmax ----
        float mx0 = -INFINITY, mx1 = -INFINITY;
#pragma unroll
        for (int nf = 0; nf < 8; nf++) {
            mx0 = fmaxf(mx0, fmaxf(s[nf][0], s[nf][1]));
            mx1 = fmaxf(mx1, fmaxf(s[nf][2], s[nf][3]));
        }
        mx0 = fmaxf(mx0, __shfl_xor_sync(0xffffffffu, mx0, 1));
        mx0 = fmaxf(mx0, __shfl_xor_sync(0xffffffffu, mx0, 2));
        mx1 = fmaxf(mx1, __shfl_xor_sync(0xffffffffu, mx1, 1));
        mx1 = fmaxf(mx1, __shfl_xor_sync(0xffffffffu, mx1, 2));
        float mn0 = fmaxf(mpr0, mx0), mn1 = fmaxf(mpr1, mx1);
        float cf0 = __expf(mpr0 - mn0), cf1 = __expf(mpr1 - mn1);
        mpr0 = mn0; mpr1 = mn1;

        float zs0 = 0.f, zs1 = 0.f, ls0 = 0.f, ls1 = 0.f;
        uint32_t mrow = (wid * 16 + r0) * RSTRIDE + quad * 4;
#pragma unroll
        for (int nf = 0; nf < 8; nf++) {
            float p0 = __expf(s[nf][0] - mn0);
            float p1 = __expf(s[nf][1] - mn0);
            float p2 = __expf(s[nf][2] - mn1);
            float p3 = __expf(s[nf][3] - mn1);
            zs0 += p0 + p1;
            zs1 += p2 + p3;
            uint32_t m01 = lds32(stg + AOFF_MS + mrow + nf * 16);
            uint32_t m23 = lds32(stg + AOFF_MS + mrow + 8 * RSTRIDE + nf * 16);
            p0 *= bf_lo(m01); p1 *= bf_hi(m01);
            p2 *= bf_lo(m23); p3 *= bf_hi(m23);
            ls0 += p0 + p1;
            ls1 += p2 + p3;
            s[nf][0] = p0; s[nf][1] = p1; s[nf][2] = p2; s[nf][3] = p3;
        }
        zs0 += __shfl_xor_sync(0xffffffffu, zs0, 1); zs0 += __shfl_xor_sync(0xffffffffu, zs0, 2);
        zs1 += __shfl_xor_sync(0xffffffffu, zs1, 1); zs1 += __shfl_xor_sync(0xffffffffu, zs1, 2);
        ls0 += __shfl_xor_sync(0xffffffffu, ls0, 1); ls0 += __shfl_xor_sync(0xffffffffu, ls0, 2);
        ls1 += __shfl_xor_sync(0xffffffffu, ls1, 1); ls1 += __shfl_xor_sync(0xffffffffu, ls1, 2);
        Zf0 = Zf0 * cf0 + zs0; Zf1 = Zf1 * cf1 + zs1;
        Lm0 = Lm0 * cf0 + ls0; Lm1 = Lm1 * cf1 + ls1;

#pragma unroll
        for (int nf = 0; nf < 8; nf++) {
            o[nf][0] *= cf0; o[nf][1] *= cf0;
            o[nf][2] *= cf1; o[nf][3] *= cf1;
        }

        // ---- O += P V (3-way split) ----
#pragma unroll
        for (int ks = 0; ks < 4; ks++) {
            uint32_t ph[4], pl[4];
            ph[0] = bfpack(s[2 * ks][0], s[2 * ks][1]);
            ph[1] = bfpack(s[2 * ks][2], s[2 * ks][3]);
            ph[2] = bfpack(s[2 * ks + 1][0], s[2 * ks + 1][1]);
            ph[3] = bfpack(s[2 * ks + 1][2], s[2 * ks + 1][3]);
            pl[0] = bfpack(s[2 * ks][0] - bf_lo(ph[0]), s[2 * ks][1] - bf_hi(ph[0]));
            pl[1] = bfpack(s[2 * ks][2] - bf_lo(ph[1]), s[2 * ks][3] - bf_hi(ph[1]));
            pl[2] = bfpack(s[2 * ks + 1][0] - bf_lo(ph[2]), s[2 * ks + 1][1] - bf_hi(ph[2]));
            pl[3] = bfpack(s[2 * ks + 1][2] - bf_lo(ph[3]), s[2 * ks + 1][3] - bf_hi(ph[3]));
            uint32_t vh[4][4], vl[4][4];
#pragma unroll
            for (int np = 0; np < 4; np++) {
                uint32_t ad = stg + np * (16 * RSTRIDE) + ks * 32 + b_base;
                ldsm_x4(vh[np], ad + AOFF_VH);
                ldsm_x4(vl[np], ad + AOFF_VL);
            }
#pragma unroll
            for (int nd = 0; nd < 8; nd++) {
                mma_bf16(o[nd], ph, &vh[nd >> 1][(nd & 1) * 2]);
                mma_bf16(o[nd], pl, &vh[nd >> 1][(nd & 1) * 2]);
                mma_bf16(o[nd], ph, &vl[nd >> 1][(nd & 1) * 2]);
            }
        }
        __syncthreads();
    }

    // ---- epilogue: z = O / (Lm + EPS*Zf) as split bf16 ----
    float inv0 = 1.0f / (Lm0 + EPS_ * Zf0);
    float inv1 = 1.0f / (Lm1 + EPS_ * Zf1);
    int row0 = q0 + wid * 16 + r0;
    int colb = h * DH_ + quad * 2;
#pragma unroll
    for (int nd = 0; nd < 8; nd++) {
        int col = colb + nd * 8;
        float z0 = o[nd][0] * inv0, z1 = o[nd][1] * inv0;
        float z2 = o[nd][2] * inv1, z3 = o[nd][3] * inv1;
        uint32_t h01 = bfpack(z0, z1);
        uint32_t h23 = bfpack(z2, z3);
        uint32_t l01 = bfpack(z0 - bf_lo(h01), z1 - bf_hi(h01));
        uint32_t l23 = bfpack(z2 - bf_lo(h23), z3 - bf_hi(h23));
        size_t i0 = ((size_t)b * L_ + row0) * DIM_ + col;
        size_t i1 = ((size_t)b * L_ + row0 + 8) * DIM_ + col;
        *(uint32_t*)(zhi + i0) = h01;
        *(uint32_t*)(zlo + i0) = l01;
        *(uint32_t*)(zhi + i1) = h23;
        *(uint32_t*)(zlo + i1) = l23;
    }
}

// ---------------------------------------------------------------------------
extern "C" void kernel_launch(void* const* d_in, const int* in_sizes, int n_in,
                              void* d_out, int out_size)
{
    const float* x    = (const float*)d_in[0];
    const float* mask = (const float*)d_in[1];
    const float* Wqkv = (const float*)d_in[2];
    const float* Wout = (const float*)d_in[3];
    const float* bout = (const float*)d_in[4];
    float* out = (float*)d_out;

    float* qkvp = nullptr;
    __nv_bfloat16 *ahi, *alo, *wqh, *wql, *woh, *wol;
    __nv_bfloat16 *qh, *ql, *kh, *kl, *vth, *vtl, *mb;
    cudaGetSymbolAddress((void**)&qkvp, g_qkv);
    cudaGetSymbolAddress((void**)&ahi, g_ahi);
    cudaGetSymbolAddress((void**)&alo, g_alo);
    cudaGetSymbolAddress((void**)&wqh, g_wqt_hi);
    cudaGetSymbolAddress((void**)&wql, g_wqt_lo);
    cudaGetSymbolAddress((void**)&woh, g_wot_hi);
    cudaGetSymbolAddress((void**)&wol, g_wot_lo);
    cudaGetSymbolAddress((void**)&qh, g_qh);
    cudaGetSymbolAddress((void**)&ql, g_ql);
    cudaGetSymbolAddress((void**)&kh, g_kh);
    cudaGetSymbolAddress((void**)&kl, g_kl);
    cudaGetSymbolAddress((void**)&vth, g_vth);
    cudaGetSymbolAddress((void**)&vtl, g_vtl);
    cudaGetSymbolAddress((void**)&mb, g_maskb);

    const int GSM = 2 * STG_BYTES;
    cudaFuncSetAttribute(mm_hmma<false>, cudaFuncAttributeMaxDynamicSharedMemorySize, GSM);
    cudaFuncSetAttribute(mm_hmma<true>,  cudaFuncAttributeMaxDynamicSharedMemorySize, GSM);
    cudaFuncSetAttribute(attn_mma, cudaFuncAttributeMaxDynamicSharedMemorySize, ATTN_SMEM_TOTAL);

    // input splits + weight transposes + mask conversion
    split_fp32<<<(B_ * L_ * DIM_ / 4 + 255) / 256, 256>>>(x, ahi, alo, B_ * L_ * DIM_ / 4);
    transpose_split<<<dim3(N3_ / 32, DIM_ / 32), dim3(32, 8)>>>(Wqkv, wqh, wql, DIM_, N3_);
    transpose_split<<<dim3(DIM_ / 32, DIM_ / 32), dim3(32, 8)>>>(Wout, woh, wol, DIM_, DIM_);
    mask_bf16<<<(B_ * L_ * L_ / 4 + 255) / 256, 256>>>(mask, mb, B_ * L_ * L_ / 4);

    // QKV projection
    mm_hmma<false><<<dim3(N3_ / 128, (B_ * L_) / 128), 256, GSM>>>(
        ahi, alo, wqh, wql, nullptr, qkvp, B_ * L_, N3_, DIM_);

    // relayout to attention operands
    qk_relayout<<<B_ * L_, 256>>>(qkvp, qh, ql, kh, kl);
    v_relayout<<<dim3(L_ / 32, DH_ / 32, B_ * H_), dim3(32, 8)>>>(qkvp, vth, vtl);

    // tensor-core flash attention -> split bf16 z
    attn_mma<<<dim3(L_ / 128, H_, B_), 256, ATTN_SMEM_TOTAL>>>(
        qh, ql, kh, kl, vth, vtl, mb, ahi, alo);

    // output projection (+bias)
    mm_hmma<true><<<dim3(DIM_ / 128, (B_ * L_) / 128), 256, GSM>>>(
        ahi, alo, woh, wol, bout, out, B_ * L_, DIM_, DIM_);
}